// round 13
// baseline (speedup 1.0000x reference)
#include <cuda_runtime.h>
#include <cuda_fp16.h>
#include <cstdint>

// ============================================================
// LoRALinear on base sm_103 (no 'a' features):
//   out = (x @ signs^T) * scale + 2 * ((x@A^T) @ B^T)
// Path: fp16 HMMA m16n8k16 with **fp16 accumulate** (2x rate on legacy
// tensor pipes), segmented per K=64 chunk and promoted into fp32 master
// accumulators each chunk. signs exact in fp16. LoRA folded as 3 fp16
// k16 steps. 512 thr / 16 warps / warp tile 32x32 / 4-stage cp.async.
// ============================================================

#define DINLINE __device__ __forceinline__

// ---------------- scratch (device globals) ----------------
__device__ __half g_xh[8192u * 4096u];   // 64 MB  x in fp16
__device__ __half g_sh[4096u * 4096u];   // 32 MB  signs in fp16 (exact)
__device__ float  g_t [8192 * 16];       // t = x @ A^T (fp32)
__device__ __half g_tA[8192 * 48];       // [t_hi | t_lo | t_hi]
__device__ __half g_tB[4096 * 48];       // [B''hi | B''hi | B''lo], B''=2B/scale

// ---------------- PTX helpers ----------------
DINLINE uint32_t smem_u32(const void* p) {
    uint32_t a;
    asm("{ .reg .u64 t; cvta.to.shared.u64 t, %1; cvt.u32.u64 %0, t; }"
        : "=r"(a) : "l"(p));
    return a;
}

DINLINE void cpa16(uint32_t s, const void* g) {
    asm volatile("cp.async.cg.shared.global [%0], [%1], 16;" :: "r"(s), "l"(g));
}
#define CP_COMMIT()  asm volatile("cp.async.commit_group;" ::: "memory")
#define CP_WAIT(n)   asm volatile("cp.async.wait_group %0;" :: "n"(n) : "memory")

#define LDSM4(r0, r1, r2, r3, addr)                                              \
    asm volatile("ldmatrix.sync.aligned.m8n8.x4.shared.b16 {%0,%1,%2,%3}, [%4];" \
                 : "=r"(r0), "=r"(r1), "=r"(r2), "=r"(r3) : "r"(addr))

// fp16 accumulate: D,C are 2 regs (4 halves)
#define MMA16816HH(d, a, b)                                                      \
    asm volatile("mma.sync.aligned.m16n8k16.row.col.f16.f16.f16.f16 "            \
                 "{%0,%1}, {%2,%3,%4,%5}, {%6,%7}, {%0,%1};"                     \
                 : "+r"((d)[0]), "+r"((d)[1])                                    \
                 : "r"((a)[0]), "r"((a)[1]), "r"((a)[2]), "r"((a)[3]),           \
                   "r"((b)[0]), "r"((b)[1]))

// ---------------- kernel 1: x f32 -> fp16 ----------------
__global__ __launch_bounds__(256) void x_h_kernel(const float* __restrict__ x) {
    size_t base = ((size_t)blockIdx.x * 256 + threadIdx.x) * 8;
    float4 a = *(const float4*)(x + base);
    float4 b = *(const float4*)(x + base + 4);
    __half2 p0 = __floats2half2_rn(a.x, a.y);
    __half2 p1 = __floats2half2_rn(a.z, a.w);
    __half2 p2 = __floats2half2_rn(b.x, b.y);
    __half2 p3 = __floats2half2_rn(b.z, b.w);
    uint4 o;
    o.x = *(uint32_t*)&p0; o.y = *(uint32_t*)&p1;
    o.z = *(uint32_t*)&p2; o.w = *(uint32_t*)&p3;
    *(uint4*)(g_xh + base) = o;
}

// ---------------- kernel 2: signs f32 -> fp16 (exact) ----------------
__global__ __launch_bounds__(256) void s_h_kernel(const float* __restrict__ s) {
    size_t base = ((size_t)blockIdx.x * 256 + threadIdx.x) * 8;
    float4 a = *(const float4*)(s + base);
    float4 b = *(const float4*)(s + base + 4);
    __half2 p0 = __floats2half2_rn(a.x, a.y);
    __half2 p1 = __floats2half2_rn(a.z, a.w);
    __half2 p2 = __floats2half2_rn(b.x, b.y);
    __half2 p3 = __floats2half2_rn(b.z, b.w);
    uint4 o;
    o.x = *(uint32_t*)&p0; o.y = *(uint32_t*)&p1;
    o.z = *(uint32_t*)&p2; o.w = *(uint32_t*)&p3;
    *(uint4*)(g_sh + base) = o;
}

// ---------------- kernel 3: t[8192,16] = x @ lora_A^T (fp32) ----------------
__global__ __launch_bounds__(256) void lora_t_kernel(const float* __restrict__ x,
                                                     const float* __restrict__ A) {
    __shared__ float4 As4[16 * 128];
    __shared__ float ts[64 * 16];
    int tid = threadIdx.x, w = tid >> 5, lane = tid & 31;

    #pragma unroll
    for (int j = 0; j < 4; j++) ts[tid * 4 + j] = 0.f;

    for (int kc = 0; kc < 4096; kc += 512) {
        __syncthreads();
        #pragma unroll
        for (int i = 0; i < 8; i++) {
            int idx = tid + 256 * i;
            int r = idx >> 7, q = idx & 127;
            As4[idx] = *(const float4*)(A + (size_t)r * 4096 + kc + q * 4);
        }
        __syncthreads();
        for (int rr = 0; rr < 8; rr++) {
            int row = blockIdx.x * 64 + w * 8 + rr;
            const float4* xr = (const float4*)(x + (size_t)row * 4096 + kc);
            float acc[16];
            #pragma unroll
            for (int r = 0; r < 16; r++) acc[r] = 0.f;
            #pragma unroll
            for (int i = 0; i < 4; i++) {
                int kq = lane + i * 32;
                float4 xv = xr[kq];
                #pragma unroll
                for (int r = 0; r < 16; r++) {
                    float4 av = As4[r * 128 + kq];
                    acc[r] += xv.x * av.x + xv.y * av.y + xv.z * av.z + xv.w * av.w;
                }
            }
            #pragma unroll
            for (int r = 0; r < 16; r++) {
                float v = acc[r];
                v += __shfl_xor_sync(0xFFFFFFFFu, v, 16);
                v += __shfl_xor_sync(0xFFFFFFFFu, v, 8);
                v += __shfl_xor_sync(0xFFFFFFFFu, v, 4);
                v += __shfl_xor_sync(0xFFFFFFFFu, v, 2);
                v += __shfl_xor_sync(0xFFFFFFFFu, v, 1);
                if (lane == 0) ts[(w * 8 + rr) * 16 + r] += v;
            }
        }
    }
    __syncthreads();
    #pragma unroll
    for (int j = 0; j < 4; j++)
        g_t[(size_t)blockIdx.x * 1024 + tid * 4 + j] = ts[tid * 4 + j];
}

// ---------------- kernel 4: pack t -> fp16 [hi | lo | hi] (48/row) ----------
__global__ __launch_bounds__(256) void t_pack_kernel() {
    int row = blockIdx.x * 256 + threadIdx.x;          // < 8192
    const float* t = g_t + (size_t)row * 16;
    __align__(16) __half o[48];
    #pragma unroll
    for (int r = 0; r < 16; r++) {
        float f = t[r];
        __half h = __float2half_rn(f);
        __half l = __float2half_rn(f - __half2float(h));
        o[r] = h; o[16 + r] = l; o[32 + r] = h;
    }
    uint4* dst = (uint4*)(g_tA + (size_t)row * 48);
    const uint4* src = (const uint4*)o;
    #pragma unroll
    for (int j = 0; j < 6; j++) dst[j] = src[j];
}

// ---------------- kernel 5: pack B'' = 2*lora_B/scale -> [hi | hi | lo] -----
__global__ __launch_bounds__(256) void b_pack_kernel(const float* __restrict__ loraB,
                                                     const float* __restrict__ scale) {
    int n = blockIdx.x * 256 + threadIdx.x;            // < 4096
    float inv = 2.0f / scale[n];
    __align__(16) __half o[48];
    #pragma unroll
    for (int r = 0; r < 16; r++) {
        float v = loraB[(size_t)n * 16 + r] * inv;
        __half h = __float2half_rn(v);
        __half l = __float2half_rn(v - __half2float(h));
        o[r] = h; o[16 + r] = h; o[32 + r] = l;
    }
    uint4* dst = (uint4*)(g_tB + (size_t)n * 48);
    const uint4* src = (const uint4*)o;
    #pragma unroll
    for (int j = 0; j < 6; j++) dst[j] = src[j];
}

// ---------------- kernel 6: main fp16 HMMA GEMM (f16 accumulate) ------------
// CTA 128x128, 512 thr, 16 warps (warp_m = wid>>2, warp_n = wid&3, tile 32x32).
// K-chunk 64 fp16. Stage: A 128x64 fp16 (16 KB, 128B rows, XOR swizzle)
// + B same = 32 KB. 4 stages = 128 KB -> 1 CTA/SM.
static constexpr int STAGE = 32768;
static constexpr int NSTAGE = 4;
static constexpr int SMEM_TOTAL = NSTAGE * STAGE;      // 131072

DINLINE void issue_normal(int m0, int n0, int c, uint32_t su, int tid) {
    #pragma unroll
    for (int i = 0; i < 2; i++) {
        int idx = tid + 512 * i;                       // < 1024 x 16B
        int row = idx >> 3, g = idx & 7;
        uint32_t off = (uint32_t)(row * 128 + g * 16) ^ (uint32_t)((row & 7) << 4);
        cpa16(su + off,         g_xh + (size_t)(m0 + row) * 4096 + c * 64 + g * 8);
        cpa16(su + 16384 + off, g_sh + (size_t)(n0 + row) * 4096 + c * 64 + g * 8);
    }
    CP_COMMIT();
}

DINLINE void issue_lora(int m0, int n0, uint32_t su, int tid) {
    #pragma unroll
    for (int i = 0; i < 2; i++) {
        int idx = tid + 512 * i;                       // < 768 used
        if (idx < 768) {
            int row = idx / 6, g = idx % 6;
            uint32_t off = (uint32_t)(row * 128 + g * 16) ^ (uint32_t)((row & 7) << 4);
            cpa16(su + off,         g_tA + (size_t)(m0 + row) * 48 + g * 8);
            cpa16(su + 16384 + off, g_tB + (size_t)(n0 + row) * 48 + g * 8);
        }
    }
    CP_COMMIT();
}

DINLINE void promote(float* f, const uint32_t* d) {
    float2 a = __half22float2(*(const __half2*)&d[0]);
    float2 b = __half22float2(*(const __half2*)&d[1]);
    f[0] += a.x; f[1] += a.y; f[2] += b.x; f[3] += b.y;
}

__global__ __launch_bounds__(512, 1) void lora_gemm_kernel(
    const float* __restrict__ scale, float* __restrict__ out) {
    extern __shared__ __align__(1024) char sm[];
    const uint32_t sbase = smem_u32(sm);
    const int tid = threadIdx.x, wid = tid >> 5, l = tid & 31;
    const int warp_m = wid >> 2, warp_n = wid & 3;
    const int n0 = blockIdx.x * 128, m0 = blockIdx.y * 128;

    float facc[2][4][4];
    #pragma unroll
    for (int i = 0; i < 2; i++)
        #pragma unroll
        for (int n = 0; n < 4; n++)
            #pragma unroll
            for (int j = 0; j < 4; j++) facc[i][n][j] = 0.f;

    const uint32_t brow  = (uint32_t)(l & 15);
    const uint32_t bhalf = (uint32_t)(l >> 4);
    const uint32_t sx    = (uint32_t)((l & 7) << 4);

    issue_normal(m0, n0, 0, sbase + 0 * STAGE, tid);
    issue_normal(m0, n0, 1, sbase + 1 * STAGE, tid);
    issue_normal(m0, n0, 2, sbase + 2 * STAGE, tid);
    issue_normal(m0, n0, 3, sbase + 3 * STAGE, tid);

    // chunks 0..63 normal + chunk 64 = lora (3 k16 steps)
    for (int c = 0; c <= 64; c++) {
        CP_WAIT(3);
        __syncthreads();

        const uint32_t As = sbase + (uint32_t)(c & 3) * STAGE;
        const uint32_t Bs = As + 16384;
        const int nk16 = (c < 64) ? 4 : 3;

        // fresh f16 segment accumulators for this chunk
        uint32_t hacc[2][4][2];
        #pragma unroll
        for (int i = 0; i < 2; i++)
            #pragma unroll
            for (int n = 0; n < 4; n++) { hacc[i][n][0] = 0u; hacc[i][n][1] = 0u; }

        for (int k16 = 0; k16 < nk16; k16++) {
            uint32_t bb[4][2];
            #pragma unroll
            for (int g = 0; g < 2; g++) {
                uint32_t addr = Bs +
                    (((uint32_t)((warp_n * 32 + g * 16 + brow) * 128)
                      + (uint32_t)(k16 * 32) + bhalf * 16) ^ sx);
                LDSM4(bb[2 * g][0], bb[2 * g + 1][0],
                      bb[2 * g][1], bb[2 * g + 1][1], addr);
            }
            #pragma unroll
            for (int i = 0; i < 2; i++) {
                uint32_t addr = As +
                    (((uint32_t)((warp_m * 32 + i * 16 + brow) * 128)
                      + (uint32_t)(k16 * 32) + bhalf * 16) ^ sx);
                uint32_t ah[4];
                LDSM4(ah[0], ah[1], ah[2], ah[3], addr);
                #pragma unroll
                for (int n = 0; n < 4; n++) MMA16816HH(hacc[i][n], ah, bb[n]);
            }
        }

        // promote chunk sums into fp32 master accumulators
        #pragma unroll
        for (int i = 0; i < 2; i++)
            #pragma unroll
            for (int n = 0; n < 4; n++) promote(facc[i][n], hacc[i][n]);

        __syncthreads();

        // refill the stage just consumed with chunk c+4
        if (c + 4 < 64)       issue_normal(m0, n0, c + 4, sbase + (uint32_t)(c & 3) * STAGE, tid);
        else if (c + 4 == 64) issue_lora(m0, n0, sbase + (uint32_t)(c & 3) * STAGE, tid);
        else                  CP_COMMIT();             // keep group arithmetic exact
    }

    // ---- epilogue: out = facc * scale[col] ----
    float* sS = (float*)sm;
    if (tid < 128) sS[tid] = scale[n0 + tid];
    __syncthreads();

    #pragma unroll
    for (int i = 0; i < 2; i++) {
        int r0 = m0 + warp_m * 32 + i * 16 + (l >> 2);
        #pragma unroll
        for (int n = 0; n < 4; n++) {
            int cl = warp_n * 32 + n * 8 + (l & 3) * 2;
            float s0 = sS[cl], s1 = sS[cl + 1];
            float2 o0 = make_float2(facc[i][n][0] * s0, facc[i][n][1] * s1);
            float2 o1 = make_float2(facc[i][n][2] * s0, facc[i][n][3] * s1);
            *(float2*)(out + (size_t)r0 * 4096 + n0 + cl) = o0;
            *(float2*)(out + (size_t)(r0 + 8) * 4096 + n0 + cl) = o1;
        }
    }
}

// ---------------- launcher ----------------
extern "C" void kernel_launch(void* const* d_in, const int* in_sizes, int n_in,
                              void* d_out, int out_size) {
    const float* x      = (const float*)d_in[0];
    const float* signs  = (const float*)d_in[1];
    const float* scale  = (const float*)d_in[2];
    const float* lora_A = (const float*)d_in[3];
    const float* lora_B = (const float*)d_in[4];
    float* out = (float*)d_out;

    x_h_kernel<<<16384, 256>>>(x);
    s_h_kernel<<<8192, 256>>>(signs);
    lora_t_kernel<<<128, 256>>>(x, lora_A);
    t_pack_kernel<<<32, 256>>>();
    b_pack_kernel<<<16, 256>>>(lora_B, scale);

    cudaFuncSetAttribute(lora_gemm_kernel,
                         cudaFuncAttributeMaxDynamicSharedMemorySize, SMEM_TOTAL);
    lora_gemm_kernel<<<dim3(32, 64), 512, SMEM_TOTAL>>>(scale, out);
}

// round 15
// speedup vs baseline: 1.2774x; 1.2774x over previous
#include <cuda_runtime.h>
#include <cuda_fp16.h>
#include <cstdint>

// ============================================================
// LoRALinear on base sm_103 (no 'a' features):
//   out = (x @ signs^T) * scale + 2 * ((x@A^T) @ B^T)
// Path: SINGLE-PASS fp16 HMMA m16n8k16, f32 accumulate (proven fastest:
// R11 = 1137us). This round: fuse x->fp16 into lora_t, unroll k16 loop.
// (Resubmission of R13 — previous run died on a container infra flake.)
// ============================================================

#define DINLINE __device__ __forceinline__

// ---------------- scratch (device globals) ----------------
__device__ __half g_xh[8192u * 4096u];   // 64 MB  x in fp16
__device__ __half g_sh[4096u * 4096u];   // 32 MB  signs in fp16 (exact)
__device__ float  g_t [8192 * 16];       // t = x @ A^T (fp32)
__device__ __half g_tA[8192 * 48];       // [t_hi | t_lo | t_hi]
__device__ __half g_tB[4096 * 48];       // [B''hi | B''hi | B''lo], B''=2B/scale

// ---------------- PTX helpers ----------------
DINLINE uint32_t smem_u32(const void* p) {
    uint32_t a;
    asm("{ .reg .u64 t; cvta.to.shared.u64 t, %1; cvt.u32.u64 %0, t; }"
        : "=r"(a) : "l"(p));
    return a;
}

DINLINE void cpa16(uint32_t s, const void* g) {
    asm volatile("cp.async.cg.shared.global [%0], [%1], 16;" :: "r"(s), "l"(g));
}
#define CP_COMMIT()  asm volatile("cp.async.commit_group;" ::: "memory")
#define CP_WAIT(n)   asm volatile("cp.async.wait_group %0;" :: "n"(n) : "memory")

#define LDSM4(r0, r1, r2, r3, addr)                                              \
    asm volatile("ldmatrix.sync.aligned.m8n8.x4.shared.b16 {%0,%1,%2,%3}, [%4];" \
                 : "=r"(r0), "=r"(r1), "=r"(r2), "=r"(r3) : "r"(addr))

#define MMA16816H(d, a, b)                                                       \
    asm volatile("mma.sync.aligned.m16n8k16.row.col.f32.f16.f16.f32 "            \
                 "{%0,%1,%2,%3}, {%4,%5,%6,%7}, {%8,%9}, {%0,%1,%2,%3};"         \
                 : "+f"((d)[0]), "+f"((d)[1]), "+f"((d)[2]), "+f"((d)[3])        \
                 : "r"((a)[0]), "r"((a)[1]), "r"((a)[2]), "r"((a)[3]),           \
                   "r"((b)[0]), "r"((b)[1]))

// ---------------- kernel 1: signs f32 -> fp16 (exact) ----------------
__global__ __launch_bounds__(256) void s_h_kernel(const float* __restrict__ s) {
    size_t base = ((size_t)blockIdx.x * 256 + threadIdx.x) * 8;
    float4 a = *(const float4*)(s + base);
    float4 b = *(const float4*)(s + base + 4);
    __half2 p0 = __floats2half2_rn(a.x, a.y);
    __half2 p1 = __floats2half2_rn(a.z, a.w);
    __half2 p2 = __floats2half2_rn(b.x, b.y);
    __half2 p3 = __floats2half2_rn(b.z, b.w);
    uint4 o;
    o.x = *(uint32_t*)&p0; o.y = *(uint32_t*)&p1;
    o.z = *(uint32_t*)&p2; o.w = *(uint32_t*)&p3;
    *(uint4*)(g_sh + base) = o;
}

// ---------------- kernel 2: t = x @ lora_A^T (fp32)  +  x -> fp16 ----------
// Fused: every x element is read exactly once here, so convert+store to g_xh
// on the fly (removes the old x_h_kernel's full extra pass over x).
__global__ __launch_bounds__(256) void lora_t_kernel(const float* __restrict__ x,
                                                     const float* __restrict__ A) {
    __shared__ float4 As4[16 * 128];
    __shared__ float ts[64 * 16];
    int tid = threadIdx.x, w = tid >> 5, lane = tid & 31;

    #pragma unroll
    for (int j = 0; j < 4; j++) ts[tid * 4 + j] = 0.f;

    for (int kc = 0; kc < 4096; kc += 512) {
        __syncthreads();
        #pragma unroll
        for (int i = 0; i < 8; i++) {
            int idx = tid + 256 * i;
            int r = idx >> 7, q = idx & 127;
            As4[idx] = *(const float4*)(A + (size_t)r * 4096 + kc + q * 4);
        }
        __syncthreads();
        for (int rr = 0; rr < 8; rr++) {
            int row = blockIdx.x * 64 + w * 8 + rr;
            const float4* xr = (const float4*)(x + (size_t)row * 4096 + kc);
            __half* xo = g_xh + (size_t)row * 4096 + kc;
            float acc[16];
            #pragma unroll
            for (int r = 0; r < 16; r++) acc[r] = 0.f;
            #pragma unroll
            for (int i = 0; i < 4; i++) {
                int kq = lane + i * 32;
                float4 xv = xr[kq];
                // fused fp16 conversion of x
                __half2 h0 = __floats2half2_rn(xv.x, xv.y);
                __half2 h1 = __floats2half2_rn(xv.z, xv.w);
                uint2 hp;
                hp.x = *(uint32_t*)&h0; hp.y = *(uint32_t*)&h1;
                *(uint2*)(xo + kq * 4) = hp;
                #pragma unroll
                for (int r = 0; r < 16; r++) {
                    float4 av = As4[r * 128 + kq];
                    acc[r] += xv.x * av.x + xv.y * av.y + xv.z * av.z + xv.w * av.w;
                }
            }
            #pragma unroll
            for (int r = 0; r < 16; r++) {
                float v = acc[r];
                v += __shfl_xor_sync(0xFFFFFFFFu, v, 16);
                v += __shfl_xor_sync(0xFFFFFFFFu, v, 8);
                v += __shfl_xor_sync(0xFFFFFFFFu, v, 4);
                v += __shfl_xor_sync(0xFFFFFFFFu, v, 2);
                v += __shfl_xor_sync(0xFFFFFFFFu, v, 1);
                if (lane == 0) ts[(w * 8 + rr) * 16 + r] += v;
            }
        }
    }
    __syncthreads();
    #pragma unroll
    for (int j = 0; j < 4; j++)
        g_t[(size_t)blockIdx.x * 1024 + tid * 4 + j] = ts[tid * 4 + j];
}

// ---------------- kernel 3: pack t -> fp16 [hi | lo | hi] (48/row) ----------
__global__ __launch_bounds__(256) void t_pack_kernel() {
    int row = blockIdx.x * 256 + threadIdx.x;          // < 8192
    const float* t = g_t + (size_t)row * 16;
    __align__(16) __half o[48];
    #pragma unroll
    for (int r = 0; r < 16; r++) {
        float f = t[r];
        __half h = __float2half_rn(f);
        __half l = __float2half_rn(f - __half2float(h));
        o[r] = h; o[16 + r] = l; o[32 + r] = h;
    }
    uint4* dst = (uint4*)(g_tA + (size_t)row * 48);
    const uint4* src = (const uint4*)o;
    #pragma unroll
    for (int j = 0; j < 6; j++) dst[j] = src[j];
}

// ---------------- kernel 4: pack B'' = 2*lora_B/scale -> [hi | hi | lo] -----
__global__ __launch_bounds__(256) void b_pack_kernel(const float* __restrict__ loraB,
                                                     const float* __restrict__ scale) {
    int n = blockIdx.x * 256 + threadIdx.x;            // < 4096
    float inv = 2.0f / scale[n];
    __align__(16) __half o[48];
    #pragma unroll
    for (int r = 0; r < 16; r++) {
        float v = loraB[(size_t)n * 16 + r] * inv;
        __half h = __float2half_rn(v);
        __half l = __float2half_rn(v - __half2float(h));
        o[r] = h; o[16 + r] = h; o[32 + r] = l;
    }
    uint4* dst = (uint4*)(g_tB + (size_t)n * 48);
    const uint4* src = (const uint4*)o;
    #pragma unroll
    for (int j = 0; j < 6; j++) dst[j] = src[j];
}

// ---------------- kernel 5: main fp16 HMMA GEMM ----------------
// CTA 128x128, 256 thr (8 warps: warp_m = wid>>1 over 32 rows, warp_n = wid&1
// over 64 cols). K-chunk 64 fp16. Stage: A 128x64 fp16 (16 KB, 128B rows,
// XOR swizzle) + B same = 32 KB. 3 stages = 96 KB -> 2 CTAs/SM.
static constexpr int STAGE = 32768;
static constexpr int NSTAGE = 3;
static constexpr int SMEM_TOTAL = NSTAGE * STAGE;      // 98304

DINLINE void issue_normal(int m0, int n0, int c, uint32_t su, int tid) {
    #pragma unroll
    for (int i = 0; i < 4; i++) {
        int idx = tid + 256 * i;                       // < 1024 x 16B (A)
        int row = idx >> 3, g = idx & 7;
        uint32_t off = (uint32_t)(row * 128 + g * 16) ^ (uint32_t)((row & 7) << 4);
        cpa16(su + off,         g_xh + (size_t)(m0 + row) * 4096 + c * 64 + g * 8);
        cpa16(su + 16384 + off, g_sh + (size_t)(n0 + row) * 4096 + c * 64 + g * 8);
    }
    CP_COMMIT();
}

DINLINE void issue_lora(int m0, int n0, uint32_t su, int tid) {
    #pragma unroll
    for (int i = 0; i < 3; i++) {
        int idx = tid + 256 * i;                       // < 768 x 16B each matrix
        int row = idx / 6, g = idx % 6;
        uint32_t off = (uint32_t)(row * 128 + g * 16) ^ (uint32_t)((row & 7) << 4);
        cpa16(su + off,         g_tA + (size_t)(m0 + row) * 48 + g * 8);
        cpa16(su + 16384 + off, g_tB + (size_t)(n0 + row) * 48 + g * 8);
    }
    CP_COMMIT();
}

// one k16 step: 6 LDSM4 + 16 MMA (A fragments hoisted before MMAs)
#define K16_STEP(k16)                                                            \
    do {                                                                         \
        uint32_t bb[8][2], ah0[4], ah1[4];                                       \
        _Pragma("unroll")                                                        \
        for (int g = 0; g < 4; g++) {                                            \
            uint32_t addr = Bs +                                                 \
                (((uint32_t)((warp_n * 64 + g * 16 + brow) * 128)                \
                  + (uint32_t)((k16) * 32) + bhalf * 16) ^ sx);                  \
            LDSM4(bb[2 * g][0], bb[2 * g + 1][0],                                \
                  bb[2 * g][1], bb[2 * g + 1][1], addr);                         \
        }                                                                        \
        {                                                                        \
            uint32_t addr0 = As +                                                \
                (((uint32_t)((warp_m * 32 + brow) * 128)                         \
                  + (uint32_t)((k16) * 32) + bhalf * 16) ^ sx);                  \
            uint32_t addr1 = As +                                                \
                (((uint32_t)((warp_m * 32 + 16 + brow) * 128)                    \
                  + (uint32_t)((k16) * 32) + bhalf * 16) ^ sx);                  \
            LDSM4(ah0[0], ah0[1], ah0[2], ah0[3], addr0);                        \
            LDSM4(ah1[0], ah1[1], ah1[2], ah1[3], addr1);                        \
        }                                                                        \
        _Pragma("unroll")                                                        \
        for (int n = 0; n < 8; n++) MMA16816H(acc[0][n], ah0, bb[n]);            \
        _Pragma("unroll")                                                        \
        for (int n = 0; n < 8; n++) MMA16816H(acc[1][n], ah1, bb[n]);            \
    } while (0)

__global__ __launch_bounds__(256, 2) void lora_gemm_kernel(
    const float* __restrict__ scale, float* __restrict__ out) {
    extern __shared__ __align__(1024) char sm[];
    const uint32_t sbase = smem_u32(sm);
    const int tid = threadIdx.x, wid = tid >> 5, l = tid & 31;
    const int warp_m = wid >> 1, warp_n = wid & 1;
    const int n0 = blockIdx.x * 128, m0 = blockIdx.y * 128;

    float acc[2][8][4];
    #pragma unroll
    for (int i = 0; i < 2; i++)
        #pragma unroll
        for (int n = 0; n < 8; n++)
            #pragma unroll
            for (int j = 0; j < 4; j++) acc[i][n][j] = 0.f;

    const uint32_t brow  = (uint32_t)(l & 15);
    const uint32_t bhalf = (uint32_t)(l >> 4);
    const uint32_t sx    = (uint32_t)((l & 7) << 4);

    issue_normal(m0, n0, 0, sbase + 0 * STAGE, tid);
    issue_normal(m0, n0, 1, sbase + 1 * STAGE, tid);
    issue_normal(m0, n0, 2, sbase + 2 * STAGE, tid);

    // chunks 0..63: fully-unrolled 4x k16; chunk 64: lora (3x k16)
    for (int c = 0; c < 64; c++) {
        CP_WAIT(2);
        __syncthreads();

        const int st = c % 3;
        const uint32_t As = sbase + (uint32_t)st * STAGE;
        const uint32_t Bs = As + 16384;

        K16_STEP(0);
        K16_STEP(1);
        K16_STEP(2);
        K16_STEP(3);

        __syncthreads();

        if (c + 3 < 64)       issue_normal(m0, n0, c + 3, sbase + (uint32_t)st * STAGE, tid);
        else if (c + 3 == 64) issue_lora(m0, n0, sbase + (uint32_t)st * STAGE, tid);
        else                  CP_COMMIT();             // keep group arithmetic exact
    }
    {   // lora chunk (stage (64 % 3) = 1)
        CP_WAIT(0);
        __syncthreads();
        const uint32_t As = sbase + (uint32_t)(64 % 3) * STAGE;
        const uint32_t Bs = As + 16384;
        K16_STEP(0);
        K16_STEP(1);
        K16_STEP(2);
        __syncthreads();
    }

    // ---- epilogue: out = acc * scale[col] ----
    float* sS = (float*)sm;
    if (tid < 128) sS[tid] = scale[n0 + tid];
    __syncthreads();

    #pragma unroll
    for (int i = 0; i < 2; i++) {
        int r0 = m0 + warp_m * 32 + i * 16 + (l >> 2);
        #pragma unroll
        for (int n = 0; n < 8; n++) {
            int cl = warp_n * 64 + n * 8 + (l & 3) * 2;
            float s0 = sS[cl], s1 = sS[cl + 1];
            float2 o0 = make_float2(acc[i][n][0] * s0, acc[i][n][1] * s1);
            float2 o1 = make_float2(acc[i][n][2] * s0, acc[i][n][3] * s1);
            *(float2*)(out + (size_t)r0 * 4096 + n0 + cl) = o0;
            *(float2*)(out + (size_t)(r0 + 8) * 4096 + n0 + cl) = o1;
        }
    }
}

// ---------------- launcher ----------------
extern "C" void kernel_launch(void* const* d_in, const int* in_sizes, int n_in,
                              void* d_out, int out_size) {
    const float* x      = (const float*)d_in[0];
    const float* signs  = (const float*)d_in[1];
    const float* scale  = (const float*)d_in[2];
    const float* lora_A = (const float*)d_in[3];
    const float* lora_B = (const float*)d_in[4];
    float* out = (float*)d_out;

    s_h_kernel<<<8192, 256>>>(signs);
    lora_t_kernel<<<128, 256>>>(x, lora_A);   // also writes g_xh (fused)
    t_pack_kernel<<<32, 256>>>();
    b_pack_kernel<<<16, 256>>>(lora_B, scale);

    cudaFuncSetAttribute(lora_gemm_kernel,
                         cudaFuncAttributeMaxDynamicSharedMemorySize, SMEM_TOTAL);
    lora_gemm_kernel<<<dim3(32, 64), 256, SMEM_TOTAL>>>(scale, out);
}